// round 1
// baseline (speedup 1.0000x reference)
#include <cuda_runtime.h>
#include <cuda_bf16.h>
#include <cstdint>

// Problem constants
#define B_      32
#define C_      3
#define H_      257
#define W_      257
#define MASK_   17
#define STRIDE_ 4
#define NW_     61                 // windows per axis
#define WSZ_    289                // 17*17
#define PLANE_  (257*257)          // 66049
#define NWIN_   (B_*C_*NW_*NW_)    // 357216 windows total
#define SW_ELEMS  ((long long)NWIN_ * WSZ_)        // 103,235,424
#define S_ELEMS   ((long long)B_ * 12 * NW_ * NW_) // 1,428,864
#define S_OFF     SW_ELEMS
#define Q_OFF     (SW_ELEMS + S_ELEMS)             // 104,664,288

// One warp per 17x17 window. 9 full 32-lane iterations cover elements 0..287;
// lane 0 handles the tail element 288. Stats reduced via warp shuffles.
__global__ __launch_bounds__(256) void leafnet_fused_kernel(
    const float* __restrict__ x, float* __restrict__ out)
{
    const int gtid = blockIdx.x * blockDim.x + threadIdx.x;
    const int wid  = gtid >> 5;
    const int lane = gtid & 31;
    if (wid >= NWIN_) return;

    // wid = ((b*3 + c)*61 + i)*61 + j
    const int j  = wid % NW_;
    const int t  = wid / NW_;
    const int i  = t % NW_;
    const int bc = t / NW_;   // b*3 + c

    const float* xb  = x + (size_t)bc * PLANE_ + (size_t)(i * STRIDE_) * W_ + j * STRIDE_;
    float* swp = out + (size_t)wid * WSZ_;
    float* qp  = out + (size_t)Q_OFF + (size_t)wid * WSZ_;

    float sum   = 0.0f;
    float sumsq = 0.0f;
    float vmin  =  1e30f;
    float vmax  = -1e30f;

    #pragma unroll
    for (int k = 0; k < 9; k++) {
        const int e = k * 32 + lane;          // 0..287
        const int u = (e * 241) >> 12;        // e / 17 (exact for e <= 288)
        const int v = e - u * 17;             // e % 17
        const float val = __ldg(xb + u * W_ + v);
        __stcs(swp + e, val);                 // streaming store: don't pollute L2
        __stcs(qp  + e, floorf(val * 64.0f)); // digitize(v, linspace(0,1,65)) - 1
        sum   += val;
        sumsq  = fmaf(val, val, sumsq);
        vmin   = fminf(vmin, val);
        vmax   = fmaxf(vmax, val);
    }
    if (lane == 0) {                          // tail element e = 288 (u=16, v=16)
        const float val = __ldg(xb + 16 * W_ + 16);
        __stcs(swp + 288, val);
        __stcs(qp  + 288, floorf(val * 64.0f));
        sum   += val;
        sumsq  = fmaf(val, val, sumsq);
        vmin   = fminf(vmin, val);
        vmax   = fmaxf(vmax, val);
    }

    // Warp reduction (butterfly)
    #pragma unroll
    for (int o = 16; o > 0; o >>= 1) {
        sum   += __shfl_xor_sync(0xFFFFFFFFu, sum,   o);
        sumsq += __shfl_xor_sync(0xFFFFFFFFu, sumsq, o);
        vmin   = fminf(vmin, __shfl_xor_sync(0xFFFFFFFFu, vmin, o));
        vmax   = fmaxf(vmax, __shfl_xor_sync(0xFFFFFFFFu, vmax, o));
    }

    if (lane == 0) {
        const float inv = 1.0f / 289.0f;
        const float mean = sum * inv;
        const float var  = fmaxf(sumsq * inv - mean * mean, 0.0f);
        const float stdv = sqrtf(var);

        const int b = bc / 3;
        const int c = bc - b * 3;
        const int pos = i * NW_ + j;
        float* sp = out + (size_t)S_OFF + (size_t)b * 12 * (NW_ * NW_);
        // channel layout: [ (max-0.5)*4 | std*4 | (max-mean)*4 | (mean-min)*4 ] x C
        sp[(0 * 3 + c) * (NW_ * NW_) + pos] = (vmax - 0.5f) * 4.0f;
        sp[(1 * 3 + c) * (NW_ * NW_) + pos] = stdv * 4.0f;
        sp[(2 * 3 + c) * (NW_ * NW_) + pos] = (vmax - mean) * 4.0f;
        sp[(3 * 3 + c) * (NW_ * NW_) + pos] = (mean - vmin) * 4.0f;
    }
}

extern "C" void kernel_launch(void* const* d_in, const int* in_sizes, int n_in,
                              void* d_out, int out_size)
{
    const float* x = (const float*)d_in[0];   // (32,3,257,257) float32
    // d_in[1] = bins (65 floats) — uniform linspace(0,1,65); digitize-1 == floor(v*64)
    float* out = (float*)d_out;

    const int threads = 256;                          // 8 warps = 8 windows / block
    const int blocks  = (NWIN_ * 32 + threads - 1) / threads;  // 44652
    leafnet_fused_kernel<<<blocks, threads>>>(x, out);
}